// round 1
// baseline (speedup 1.0000x reference)
#include <cuda_runtime.h>

// y[m,n] = sum_k x[m,k] * (mask[n,k]*W[n,k]) + b[n]
// M=16384, K=2048, N=8192, all fp32.
// Strategy: mask is ~98% sparse & static -> per 32-wide n-tile, build the union
// list of used k indices + packed dense weight panel, then run a register-tiled
// GEMM over the compacted K dimension only.

#define M_DIM 16384
#define K_DIM 2048
#define N_DIM 8192
#define TN 32
#define NTILES (N_DIM / TN)   // 256
#define TM 128
#define KCHUNK 32

// Static scratch (no allocations allowed).
__device__ int   g_kidx[NTILES * K_DIM];                 // 2 MB
__device__ float g_Wp[(size_t)NTILES * K_DIM * TN];      // 64 MB  [tile][j][nn]
__device__ int   g_kpad[NTILES];

// ---------------------------------------------------------------------------
// Precompute: per n-tile, union of used k's (ordered) + packed masked weights.
// Fully deterministic (ordered bitmask compaction).
// ---------------------------------------------------------------------------
__global__ void precompute_kernel(const float* __restrict__ W,
                                  const float* __restrict__ mask) {
    const int t  = blockIdx.x;
    const int n0 = t * TN;
    const int tid = threadIdx.x;

    __shared__ unsigned int words[K_DIM / 32];  // 64 bitmask words
    __shared__ int cnts[K_DIM / 32];
    __shared__ int s_cnt, s_kpad;

    for (int w = tid; w < K_DIM / 32; w += blockDim.x) words[w] = 0u;
    __syncthreads();

    // Mark k's used by any of the 32 columns in this tile.
    for (int k = tid; k < K_DIM; k += blockDim.x) {
        bool used = false;
        #pragma unroll 4
        for (int nn = 0; nn < TN; ++nn)
            used |= (mask[(size_t)(n0 + nn) * K_DIM + k] != 0.0f);
        if (used) atomicOr(&words[k >> 5], 1u << (k & 31));
    }
    __syncthreads();

    if (tid < K_DIM / 32) cnts[tid] = __popc(words[tid]);
    __syncthreads();

    // Ordered compaction: each of 64 threads emits its word's set bits.
    if (tid < K_DIM / 32) {
        int base = 0;
        for (int u = 0; u < tid; ++u) base += cnts[u];
        unsigned int wv = words[tid];
        int k0 = tid * 32;
        while (wv) {
            int b = __ffs(wv) - 1;
            wv &= wv - 1;
            g_kidx[t * K_DIM + (base++)] = k0 + b;
        }
    }
    if (tid == 0) {
        int cnt = 0;
        for (int u = 0; u < K_DIM / 32; ++u) cnt += cnts[u];
        int kpad = (cnt + KCHUNK - 1) / KCHUNK * KCHUNK;
        if (kpad > K_DIM) kpad = K_DIM;
        for (int j = cnt; j < kpad; ++j) g_kidx[t * K_DIM + j] = 0;  // pad idx
        s_cnt = cnt; s_kpad = kpad;
        g_kpad[t] = kpad;
    }
    __syncthreads();

    const int cnt = s_cnt, kpad = s_kpad;
    // Pack masked weights: Wp[t][j][nn]; padded j gets zero weight.
    const int total = kpad * TN;
    for (int e = tid; e < total; e += blockDim.x) {
        int nn = e / kpad;
        int j  = e % kpad;
        int k  = g_kidx[t * K_DIM + j];
        float wv = 0.0f;
        if (j < cnt) {
            size_t off = (size_t)(n0 + nn) * K_DIM + k;
            wv = mask[off] * W[off];
        }
        g_Wp[((size_t)t * K_DIM + j) * TN + nn] = wv;
    }
}

// ---------------------------------------------------------------------------
// Main gather-GEMM over compacted K.
// Block: 128 m x 32 n, 128 threads, thread tile 8m x 4n, K staged in 32-chunks.
// ---------------------------------------------------------------------------
__global__ void __launch_bounds__(128)
spmm_kernel(const float* __restrict__ x,
            const float* __restrict__ bias,
            float* __restrict__ out) {
    const int t    = blockIdx.y;
    const int m0   = blockIdx.x * TM;
    const int n0   = t * TN;
    const int kpad = g_kpad[t];
    const int tid  = threadIdx.x;
    const int tm   = tid & 15;    // 0..15 -> m rows tm + 16*i
    const int tn   = tid >> 4;    // 0..7  -> n cols tn*4 .. tn*4+3

    __shared__ int s_kidx[KCHUNK];
    __shared__ __align__(16) float s_W[KCHUNK * TN];          // [kk][nn]
    __shared__ __align__(16) float s_X[KCHUNK * (TM + 1)];    // [kk][mi], pad 1

    float acc[8][4];
    #pragma unroll
    for (int i = 0; i < 8; ++i)
        #pragma unroll
        for (int j = 0; j < 4; ++j) acc[i][j] = 0.0f;

    const int*   kidx_t = g_kidx + t * K_DIM;
    const float* Wp_t   = g_Wp + (size_t)t * K_DIM * TN;

    for (int kc = 0; kc < kpad; kc += KCHUNK) {
        if (tid < KCHUNK) s_kidx[tid] = kidx_t[kc + tid];
        #pragma unroll
        for (int e = tid; e < KCHUNK * TN; e += 128)
            s_W[e] = Wp_t[(size_t)kc * TN + e];
        __syncthreads();

        // Gather x into SMEM: warp lanes span kk (scattered within one x row).
        #pragma unroll
        for (int it = 0; it < (KCHUNK * TM) / 128; ++it) {  // 32 iters
            int e  = tid + it * 128;
            int kk = e & (KCHUNK - 1);
            int mi = e >> 5;           // e / KCHUNK
            s_X[kk * (TM + 1) + mi] =
                x[(size_t)(m0 + mi) * K_DIM + s_kidx[kk]];
        }
        __syncthreads();

        #pragma unroll 8
        for (int kk = 0; kk < KCHUNK; ++kk) {
            float xa[8];
            #pragma unroll
            for (int i = 0; i < 8; ++i)
                xa[i] = s_X[kk * (TM + 1) + tm + 16 * i];
            float4 wb = *(const float4*)&s_W[kk * TN + tn * 4];
            #pragma unroll
            for (int i = 0; i < 8; ++i) {
                acc[i][0] += xa[i] * wb.x;
                acc[i][1] += xa[i] * wb.y;
                acc[i][2] += xa[i] * wb.z;
                acc[i][3] += xa[i] * wb.w;
            }
        }
        __syncthreads();
    }

    float4 bv = *(const float4*)&bias[n0 + tn * 4];
    #pragma unroll
    for (int i = 0; i < 8; ++i) {
        int row = m0 + tm + 16 * i;
        float4 o;
        o.x = acc[i][0] + bv.x;
        o.y = acc[i][1] + bv.y;
        o.z = acc[i][2] + bv.z;
        o.w = acc[i][3] + bv.w;
        *(float4*)&out[(size_t)row * N_DIM + n0 + tn * 4] = o;
    }
}

// ---------------------------------------------------------------------------
extern "C" void kernel_launch(void* const* d_in, const int* in_sizes, int n_in,
                              void* d_out, int out_size) {
    const float* x    = (const float*)d_in[0];  // [16384, 2048]
    const float* W    = (const float*)d_in[1];  // [8192, 2048]
    const float* bias = (const float*)d_in[2];  // [8192]
    const float* mask = (const float*)d_in[3];  // [8192, 2048]
    float* out = (float*)d_out;                 // [16384, 8192]

    precompute_kernel<<<NTILES, 256>>>(W, mask);

    dim3 grid(M_DIM / TM, NTILES);
    spmm_kernel<<<grid, 128>>>(x, bias, out);
}

// round 2
// speedup vs baseline: 1.4180x; 1.4180x over previous
#include <cuda_runtime.h>

// y[m,n] = sum_k x[m,k] * (mask[n,k]*W[n,k]) + b[n]
// M=16384, K=2048, N=8192, fp32.
//
// Pipeline:
//  1. rowscan:    per output row n, 64-word k-bitmask + heavy flag (>=256 nnz)
//  2. tile_pack:  per 32-wide n-tile, union of non-heavy rows' bitmasks ->
//                 ordered k index list + packed masked weight panel
//  3. heavy_list: deterministic ordered list of heavy columns
//  4. spmm:       register-tiled gather GEMM over compacted K (8m x 8n per
//                 thread, packed fma.rn.f32x2 accumulation)
//  5. dense_cols: recompute heavy columns densely, overwrite their output

#define M_DIM 16384
#define K_DIM 2048
#define N_DIM 8192
#define TN 32
#define NTILES (N_DIM / TN)   // 256
#define TM 256
#define KCHUNK 32
#define SX_STRIDE 257          // odd stride -> conflict-free column writes
#define HEAVY_THRESH 256

// Static scratch (allocations are forbidden).
__device__ unsigned g_rowbits[(size_t)N_DIM * 64];        // 2 MB
__device__ int      g_heavyflag[N_DIM];
__device__ int      g_heavy[N_DIM];
__device__ int      g_nheavy;
__device__ int      g_kidx[NTILES * K_DIM];               // 2 MB
__device__ int      g_kpad[NTILES];
__device__ float    g_Wp[(size_t)NTILES * K_DIM * TN];    // 64 MB [tile][j][nn]

// ---------------------------------------------------------------------------
// 1. Per-row bitmask + heavy flag. One warp per output row.
// ---------------------------------------------------------------------------
__global__ void rowscan_kernel(const float* __restrict__ mask) {
    int warp = (blockIdx.x * blockDim.x + threadIdx.x) >> 5;
    int lane = threadIdx.x & 31;
    if (warp >= N_DIM) return;
    const float* row = mask + (size_t)warp * K_DIM;
    int cnt = 0;
    #pragma unroll 8
    for (int w = 0; w < K_DIM / 32; ++w) {
        float v = row[w * 32 + lane];
        unsigned b = __ballot_sync(0xffffffffu, v != 0.0f);
        if (lane == 0) g_rowbits[(size_t)warp * 64 + w] = b;
        cnt += __popc(b);
    }
    if (lane == 0) g_heavyflag[warp] = (cnt >= HEAVY_THRESH) ? 1 : 0;
}

// ---------------------------------------------------------------------------
// 2. Per n-tile: union bitmask (excluding heavy rows), ordered compaction,
//    packed masked weights.
// ---------------------------------------------------------------------------
__global__ void tile_pack_kernel(const float* __restrict__ W,
                                 const float* __restrict__ mask) {
    const int t = blockIdx.x, n0 = t * TN, tid = threadIdx.x;
    __shared__ unsigned words[64];
    __shared__ int cnts[64];
    __shared__ int hflag[TN];
    __shared__ int s_cnt, s_kpad;

    if (tid < TN) hflag[tid] = g_heavyflag[n0 + tid];
    __syncthreads();

    if (tid < 64) {
        unsigned u = 0;
        #pragma unroll 4
        for (int nn = 0; nn < TN; ++nn)
            if (!hflag[nn]) u |= g_rowbits[(size_t)(n0 + nn) * 64 + tid];
        words[tid] = u;
        cnts[tid] = __popc(u);
    }
    __syncthreads();

    if (tid < 64) {
        int base = 0;
        for (int u = 0; u < tid; ++u) base += cnts[u];
        unsigned wv = words[tid];
        int k0 = tid * 32;
        while (wv) {
            int b = __ffs(wv) - 1;
            wv &= wv - 1;
            g_kidx[t * K_DIM + base++] = k0 + b;
        }
    }
    if (tid == 0) {
        int cnt = 0;
        for (int u = 0; u < 64; ++u) cnt += cnts[u];
        int kpad = (cnt + KCHUNK - 1) / KCHUNK * KCHUNK;
        if (kpad > K_DIM) kpad = K_DIM;
        for (int j = cnt; j < kpad; ++j) g_kidx[t * K_DIM + j] = 0;
        s_cnt = cnt; s_kpad = kpad;
        g_kpad[t] = kpad;
    }
    __syncthreads();

    const int cnt = s_cnt, kpad = s_kpad;
    for (int e = tid; e < kpad * TN; e += blockDim.x) {
        int nn = e & (TN - 1);
        int j  = e >> 5;
        float wv = 0.0f;
        if (j < cnt && !hflag[nn]) {
            int k = g_kidx[t * K_DIM + j];
            size_t off = (size_t)(n0 + nn) * K_DIM + k;
            wv = mask[off] * W[off];
        }
        g_Wp[((size_t)t * K_DIM + j) * TN + nn] = wv;
    }
}

// ---------------------------------------------------------------------------
// 3. Ordered heavy-column list (single block, deterministic).
// ---------------------------------------------------------------------------
__global__ void heavy_list_kernel() {
    const int tid = threadIdx.x;
    const int per = N_DIM / 256;  // 32
    __shared__ int cnt[256];
    __shared__ int off[257];
    int c = 0;
    for (int i = 0; i < per; ++i) c += g_heavyflag[tid * per + i];
    cnt[tid] = c;
    __syncthreads();
    if (tid == 0) {
        off[0] = 0;
        for (int i = 0; i < 256; ++i) off[i + 1] = off[i] + cnt[i];
        g_nheavy = off[256];
    }
    __syncthreads();
    int o = off[tid];
    for (int i = 0; i < per; ++i) {
        int n = tid * per + i;
        if (g_heavyflag[n]) g_heavy[o++] = n;
    }
}

// ---------------------------------------------------------------------------
// 4. Main gather-GEMM over compacted K.
//    Block: 256m x 32n, 128 threads, thread tile 8m x 8n (4 f32x2 pairs).
// ---------------------------------------------------------------------------
__device__ __forceinline__ unsigned long long splat2(float v) {
    unsigned long long r;
    asm("mov.b64 %0, {%1, %1};" : "=l"(r) : "f"(v));
    return r;
}
__device__ __forceinline__ void fma2(unsigned long long& acc,
                                     unsigned long long a,
                                     unsigned long long b) {
    asm("fma.rn.f32x2 %0, %1, %2, %0;" : "+l"(acc) : "l"(a), "l"(b));
}
__device__ __forceinline__ void unpack2(unsigned long long a, float& lo, float& hi) {
    asm("mov.b64 {%0, %1}, %2;" : "=f"(lo), "=f"(hi) : "l"(a));
}

__global__ void __launch_bounds__(128)
spmm_kernel(const float* __restrict__ x,
            const float* __restrict__ bias,
            float* __restrict__ out) {
    const int t    = blockIdx.y;
    const int m0   = blockIdx.x * TM;
    const int n0   = t * TN;
    const int kpad = g_kpad[t];
    const int tid  = threadIdx.x;
    const int tm   = tid & 31;    // 0..31: rows tm + 32*i
    const int tn   = tid >> 5;    // 0..3 : cols tn*8 .. tn*8+7

    __shared__ __align__(16) float s_W[KCHUNK * TN];          // 4 KB
    __shared__ __align__(16) float s_X[KCHUNK * SX_STRIDE];   // 32.9 KB

    unsigned long long acc[8][4];
    #pragma unroll
    for (int i = 0; i < 8; ++i)
        #pragma unroll
        for (int j = 0; j < 4; ++j) acc[i][j] = 0ull;

    const int*   kidx_t = g_kidx + t * K_DIM;
    const float* Wp_t   = g_Wp + (size_t)t * K_DIM * TN;

    for (int kc = 0; kc < kpad; kc += KCHUNK) {
        __syncthreads();  // previous compute done before refill
        const int kid = kidx_t[kc + tm];   // this lane's gather column

        // Fill s_W (1024 floats) with two float4 per thread.
        {
            const float4* src = (const float4*)(Wp_t + (size_t)kc * TN);
            ((float4*)s_W)[tid]       = src[tid];
            ((float4*)s_W)[tid + 128] = src[tid + 128];
        }
        // Gather x: lane handles k=kid (kk=tm), rows tn + 4*it.
        #pragma unroll
        for (int it = 0; it < TM / 4; ++it) {
            int mi = tn + 4 * it;
            s_X[tm * SX_STRIDE + mi] = x[(size_t)(m0 + mi) * K_DIM + kid];
        }
        __syncthreads();

        #pragma unroll
        for (int kk = 0; kk < KCHUNK; ++kk) {
            unsigned long long xa2[8];
            #pragma unroll
            for (int i = 0; i < 8; ++i)
                xa2[i] = splat2(s_X[kk * SX_STRIDE + tm + 32 * i]);
            const unsigned long long* wp =
                (const unsigned long long*)&s_W[kk * TN + tn * 8];
            unsigned long long w2[4];
            #pragma unroll
            for (int j = 0; j < 4; ++j) w2[j] = wp[j];
            #pragma unroll
            for (int i = 0; i < 8; ++i)
                #pragma unroll
                for (int j = 0; j < 4; ++j)
                    fma2(acc[i][j], xa2[i], w2[j]);
        }
    }

    // Epilogue: unpack, add bias, store two float4 per row.
    float4 bb0 = *(const float4*)&bias[n0 + tn * 8];
    float4 bb1 = *(const float4*)&bias[n0 + tn * 8 + 4];
    #pragma unroll
    for (int i = 0; i < 8; ++i) {
        int row = m0 + tm + 32 * i;
        float o[8];
        #pragma unroll
        for (int j = 0; j < 4; ++j) unpack2(acc[i][j], o[2 * j], o[2 * j + 1]);
        float4 v0 = make_float4(o[0] + bb0.x, o[1] + bb0.y, o[2] + bb0.z, o[3] + bb0.w);
        float4 v1 = make_float4(o[4] + bb1.x, o[5] + bb1.y, o[6] + bb1.z, o[7] + bb1.w);
        float* dst = out + (size_t)row * N_DIM + n0 + tn * 8;
        *(float4*)dst       = v0;
        *(float4*)(dst + 4) = v1;
    }
}

// ---------------------------------------------------------------------------
// 5. Heavy columns: full dense dot per (column, row), overwrites output.
//    Persistent grid; runs AFTER spmm so its writes win.
// ---------------------------------------------------------------------------
__global__ void dense_cols_kernel(const float* __restrict__ x,
                                  const float* __restrict__ W,
                                  const float* __restrict__ mask,
                                  const float* __restrict__ bias,
                                  float* __restrict__ out) {
    const int nh = g_nheavy;
    if (nh == 0) return;
    const int wflat = (blockIdx.x * blockDim.x + threadIdx.x) >> 5;  // 0..8191
    const int lane  = threadIdx.x & 31;
    const int units_per_col = M_DIM / 2;   // 2 rows per unit
    const int total = nh * units_per_col;
    for (int u = wflat; u < total; u += 8192) {
        int c   = g_heavy[u / units_per_col];
        int seg = u % units_per_col;
        int r0  = seg * 2;
        const float* wr = W    + (size_t)c * K_DIM;
        const float* mr = mask + (size_t)c * K_DIM;
        const float* x0 = x + (size_t)r0 * K_DIM;
        float s0 = 0.0f, s1 = 0.0f;
        #pragma unroll 4
        for (int k = lane; k < K_DIM; k += 32) {
            float wv = mr[k] * wr[k];
            s0 += x0[k] * wv;
            s1 += x0[K_DIM + k] * wv;
        }
        #pragma unroll
        for (int d = 16; d; d >>= 1) {
            s0 += __shfl_xor_sync(0xffffffffu, s0, d);
            s1 += __shfl_xor_sync(0xffffffffu, s1, d);
        }
        if (lane == 0) {
            float b = bias[c];
            out[(size_t)r0 * N_DIM + c]       = s0 + b;
            out[(size_t)(r0 + 1) * N_DIM + c] = s1 + b;
        }
    }
}

// ---------------------------------------------------------------------------
extern "C" void kernel_launch(void* const* d_in, const int* in_sizes, int n_in,
                              void* d_out, int out_size) {
    const float* x    = (const float*)d_in[0];  // [16384, 2048]
    const float* W    = (const float*)d_in[1];  // [8192, 2048]
    const float* bias = (const float*)d_in[2];  // [8192]
    const float* mask = (const float*)d_in[3];  // [8192, 2048]
    float* out = (float*)d_out;                 // [16384, 8192]

    rowscan_kernel<<<N_DIM / 8, 256>>>(mask);          // 8 warps/block
    tile_pack_kernel<<<NTILES, 256>>>(W, mask);
    heavy_list_kernel<<<1, 256>>>();
    dim3 grid(M_DIM / TM, NTILES);
    spmm_kernel<<<grid, 128>>>(x, bias, out);
    dense_cols_kernel<<<1024, 256>>>(x, W, mask, bias, out);
}

// round 3
// speedup vs baseline: 1.4751x; 1.0402x over previous
#include <cuda_runtime.h>

// y[m,n] = sum_k x[m,k] * (mask[n,k]*W[n,k]) + b[n]
// M=16384, K=2048, N=8192, fp32.
//
// Pipeline:
//  1. rowscan:    per output row n, 64-word k-bitmask + heavy flag (>=256 nnz)
//  2. tile_pack:  per 24-wide n-tile, union of non-heavy rows' bitmasks ->
//                 ordered k index list + packed masked weight panel
//  3. heavy_list: deterministic ordered list of heavy columns
//  4. transpose:  xT[k][m]  (so the spmm gather is fully coalesced)
//  5. spmm:       gather GEMM over compacted K; cp.async double-buffered,
//                 f32x2 accumulation over m-pairs
//  6. dense_cols: recompute heavy columns densely, overwrite their output

#define M_DIM 16384
#define K_DIM 2048
#define N_DIM 8192
#define TN 24
#define NTILES ((N_DIM + TN - 1) / TN)   // 342
#define TM 256
#define KCHUNK 16
#define HEAVY_THRESH 256

// Static scratch (allocations are forbidden).
__device__ unsigned g_rowbits[(size_t)N_DIM * 64];            // 2 MB
__device__ int      g_heavyflag[N_DIM];
__device__ int      g_heavy[N_DIM];
__device__ int      g_nheavy;
__device__ int      g_kidx[NTILES * K_DIM];                   // 2.8 MB
__device__ int      g_kpad[NTILES];
__device__ float    g_Wp[(size_t)NTILES * K_DIM * TN];        // 67 MB [tile][j][nn]
__device__ float    g_xT[(size_t)K_DIM * M_DIM];              // 128 MB

// ---------------------------------------------------------------------------
// helpers
// ---------------------------------------------------------------------------
__device__ __forceinline__ unsigned long long splat2(float v) {
    unsigned long long r;
    asm("mov.b64 %0, {%1, %1};" : "=l"(r) : "f"(v));
    return r;
}
__device__ __forceinline__ void fma2(unsigned long long& acc,
                                     unsigned long long a,
                                     unsigned long long b) {
    asm("fma.rn.f32x2 %0, %1, %2, %0;" : "+l"(acc) : "l"(a), "l"(b));
}
__device__ __forceinline__ void unpack2(unsigned long long a, float& lo, float& hi) {
    asm("mov.b64 {%0, %1}, %2;" : "=f"(lo), "=f"(hi) : "l"(a));
}
__device__ __forceinline__ void cpasync16(unsigned dst, const void* src) {
    asm volatile("cp.async.cg.shared.global [%0], [%1], 16;" :: "r"(dst), "l"(src));
}
__device__ __forceinline__ void cp_commit() { asm volatile("cp.async.commit_group;"); }
template <int N>
__device__ __forceinline__ void cp_wait() { asm volatile("cp.async.wait_group %0;" :: "n"(N)); }

// ---------------------------------------------------------------------------
// 1. Per-row bitmask + heavy flag. One warp per output row.
// ---------------------------------------------------------------------------
__global__ void rowscan_kernel(const float* __restrict__ mask) {
    int warp = (blockIdx.x * blockDim.x + threadIdx.x) >> 5;
    int lane = threadIdx.x & 31;
    if (warp >= N_DIM) return;
    const float* row = mask + (size_t)warp * K_DIM;
    int cnt = 0;
    #pragma unroll 8
    for (int w = 0; w < K_DIM / 32; ++w) {
        float v = row[w * 32 + lane];
        unsigned b = __ballot_sync(0xffffffffu, v != 0.0f);
        if (lane == 0) g_rowbits[(size_t)warp * 64 + w] = b;
        cnt += __popc(b);
    }
    if (lane == 0) g_heavyflag[warp] = (cnt >= HEAVY_THRESH) ? 1 : 0;
}

// ---------------------------------------------------------------------------
// 2. Per n-tile: union bitmask (excluding heavy rows), ordered compaction,
//    packed masked weights.
// ---------------------------------------------------------------------------
__global__ void tile_pack_kernel(const float* __restrict__ W,
                                 const float* __restrict__ mask) {
    const int t = blockIdx.x, n0 = t * TN, tid = threadIdx.x;
    __shared__ unsigned words[64];
    __shared__ int cnts[64];
    __shared__ int hflag[TN];
    __shared__ int s_cnt, s_kpad;

    if (tid < TN)
        hflag[tid] = (n0 + tid < N_DIM) ? g_heavyflag[n0 + tid] : 1;
    __syncthreads();

    if (tid < 64) {
        unsigned u = 0;
        #pragma unroll 4
        for (int nn = 0; nn < TN; ++nn)
            if (!hflag[nn]) u |= g_rowbits[(size_t)(n0 + nn) * 64 + tid];
        words[tid] = u;
        cnts[tid] = __popc(u);
    }
    __syncthreads();

    if (tid < 64) {
        int base = 0;
        for (int u = 0; u < tid; ++u) base += cnts[u];
        unsigned wv = words[tid];
        int k0 = tid * 32;
        while (wv) {
            int b = __ffs(wv) - 1;
            wv &= wv - 1;
            g_kidx[t * K_DIM + base++] = k0 + b;
        }
    }
    if (tid == 0) {
        int cnt = 0;
        for (int u = 0; u < 64; ++u) cnt += cnts[u];
        int kpad = (cnt + KCHUNK - 1) / KCHUNK * KCHUNK;
        if (kpad == 0) kpad = KCHUNK;
        if (kpad > K_DIM) kpad = K_DIM;
        for (int j = cnt; j < kpad; ++j) g_kidx[t * K_DIM + j] = 0;
        s_cnt = cnt; s_kpad = kpad;
        g_kpad[t] = kpad;
    }
    __syncthreads();

    const int cnt = s_cnt, kpad = s_kpad;
    for (int e = tid; e < kpad * TN; e += blockDim.x) {
        int j  = e / TN;
        int nn = e - j * TN;
        float wv = 0.0f;
        if (j < cnt && !hflag[nn] && (n0 + nn) < N_DIM) {
            int k = g_kidx[t * K_DIM + j];
            size_t off = (size_t)(n0 + nn) * K_DIM + k;
            wv = mask[off] * W[off];
        }
        g_Wp[((size_t)t * K_DIM + j) * TN + nn] = wv;
    }
}

// ---------------------------------------------------------------------------
// 3. Ordered heavy-column list (single block, deterministic).
// ---------------------------------------------------------------------------
__global__ void heavy_list_kernel() {
    const int tid = threadIdx.x;
    const int per = N_DIM / 256;  // 32
    __shared__ int cnt[256];
    __shared__ int off[257];
    int c = 0;
    for (int i = 0; i < per; ++i) c += g_heavyflag[tid * per + i];
    cnt[tid] = c;
    __syncthreads();
    if (tid == 0) {
        off[0] = 0;
        for (int i = 0; i < 256; ++i) off[i + 1] = off[i] + cnt[i];
        g_nheavy = off[256];
    }
    __syncthreads();
    int o = off[tid];
    for (int i = 0; i < per; ++i) {
        int n = tid * per + i;
        if (g_heavyflag[n]) g_heavy[o++] = n;
    }
}

// ---------------------------------------------------------------------------
// 4. Transpose x -> xT[k][m].
// ---------------------------------------------------------------------------
__global__ void transpose_kernel(const float* __restrict__ x,
                                 float* __restrict__ xT) {
    __shared__ float tile[32][33];
    const int k0 = blockIdx.x * 32;
    const int m0 = blockIdx.y * 32;
    const int tx = threadIdx.x, ty = threadIdx.y;   // 32 x 8
    #pragma unroll
    for (int j = 0; j < 32; j += 8)
        tile[ty + j][tx] = x[(size_t)(m0 + ty + j) * K_DIM + k0 + tx];
    __syncthreads();
    #pragma unroll
    for (int j = 0; j < 32; j += 8)
        xT[(size_t)(k0 + ty + j) * M_DIM + m0 + tx] = tile[tx][ty + j];
}

// ---------------------------------------------------------------------------
// 5. Main gather-GEMM over compacted K.
//    Block: 256m x 24n, 128 threads; thread tile = 4 m-pairs x 6 n (f32x2
//    over m-pairs). cp.async double-buffered K staging from xT (coalesced).
// ---------------------------------------------------------------------------
__global__ void __launch_bounds__(128, 5)
spmm_kernel(const float* __restrict__ xT,
            const float* __restrict__ bias,
            float* __restrict__ out) {
    const int t    = blockIdx.y;
    const int m0   = blockIdx.x * TM;
    const int n0   = t * TN;
    const int kpad = g_kpad[t];
    const int tid  = threadIdx.x;
    const int tm   = tid & 31;     // m-pair base: 2*tm + 64*i
    const int tn   = tid >> 5;     // n cols tn*6 .. tn*6+5

    __shared__ __align__(16) float s_X[2][KCHUNK * TM];   // 32 KB
    __shared__ __align__(16) float s_W[2][KCHUNK * TN];   // 3 KB

    unsigned long long acc[4][6];
    #pragma unroll
    for (int i = 0; i < 4; ++i)
        #pragma unroll
        for (int j = 0; j < 6; ++j) acc[i][j] = 0ull;

    const int*   kidx = g_kidx + t * K_DIM;
    const float* Wp   = g_Wp + (size_t)t * K_DIM * TN;

    // ---- prefetch of one KCHUNK into buffer `buf` -------------------------
    auto prefetch = [&](int kc, int buf) {
        // x: KCHUNK rows x TM floats = 1024 float4 ; 8 per thread
        #pragma unroll
        for (int it = 0; it < 8; ++it) {
            int f  = it * 128 + tid;
            int kk = f >> 6;          // TM/4 = 64 float4 per row
            int c4 = f & 63;
            const float* src = xT + ((size_t)kidx[kc + kk] << 14) + m0 + c4 * 4;
            unsigned dst = (unsigned)__cvta_generic_to_shared(
                &s_X[buf][kk * TM + c4 * 4]);
            cpasync16(dst, src);
        }
        // W: KCHUNK x 24 = 96 float4 ; threads 0..95
        if (tid < 96) {
            int kk = tid / 6, c4 = tid - kk * 6;
            const float* src = Wp + (size_t)(kc + kk) * TN + c4 * 4;
            unsigned dst = (unsigned)__cvta_generic_to_shared(
                &s_W[buf][kk * TN + c4 * 4]);
            cpasync16(dst, src);
        }
    };

    prefetch(0, 0);
    cp_commit();
    const int nch = kpad >> 4;

    for (int c = 0; c < nch; ++c) {
        const int buf = c & 1;
        __syncthreads();                       // buffer buf^1 free for refill
        if (c + 1 < nch) {
            prefetch((c + 1) << 4, buf ^ 1);
            cp_commit();
            cp_wait<1>();                      // chunk c resident
        } else {
            cp_wait<0>();
        }
        __syncthreads();

        const float* sx = &s_X[buf][0];
        const float* sw = &s_W[buf][0];
        #pragma unroll
        for (int kk = 0; kk < KCHUNK; ++kk) {
            unsigned long long x2[4];
            #pragma unroll
            for (int i = 0; i < 4; ++i)
                x2[i] = *(const unsigned long long*)
                        &sx[kk * TM + 2 * tm + 64 * i];
            unsigned long long w2[6];
            #pragma unroll
            for (int j = 0; j < 6; ++j)
                w2[j] = splat2(sw[kk * TN + tn * 6 + j]);
            #pragma unroll
            for (int i = 0; i < 4; ++i)
                #pragma unroll
                for (int j = 0; j < 6; ++j)
                    fma2(acc[i][j], x2[i], w2[j]);
        }
    }

    // ---- epilogue ---------------------------------------------------------
    float bb[6];
    #pragma unroll
    for (int j = 0; j < 6; ++j) {
        int n = n0 + tn * 6 + j;
        bb[j] = (n < N_DIM) ? bias[n] : 0.0f;
    }
    #pragma unroll
    for (int i = 0; i < 4; ++i) {
        float lo[6], hi[6];
        #pragma unroll
        for (int j = 0; j < 6; ++j) unpack2(acc[i][j], lo[j], hi[j]);
        int r0 = m0 + 2 * tm + 64 * i;
        float* d0 = out + (size_t)r0 * N_DIM + n0 + tn * 6;
        float* d1 = d0 + N_DIM;
        #pragma unroll
        for (int j = 0; j < 3; ++j) {
            int n = n0 + tn * 6 + 2 * j;
            if (n + 1 < N_DIM) {
                *(float2*)(d0 + 2 * j) = make_float2(lo[2*j] + bb[2*j], lo[2*j+1] + bb[2*j+1]);
                *(float2*)(d1 + 2 * j) = make_float2(hi[2*j] + bb[2*j], hi[2*j+1] + bb[2*j+1]);
            } else if (n < N_DIM) {
                d0[2 * j] = lo[2 * j] + bb[2 * j];
                d1[2 * j] = hi[2 * j] + bb[2 * j];
            }
        }
    }
}

// ---------------------------------------------------------------------------
// 6. Heavy columns: full dense dot per (column, row-pair), overwrites output.
// ---------------------------------------------------------------------------
__global__ void dense_cols_kernel(const float* __restrict__ x,
                                  const float* __restrict__ W,
                                  const float* __restrict__ mask,
                                  const float* __restrict__ bias,
                                  float* __restrict__ out) {
    const int nh = g_nheavy;
    if (nh == 0) return;
    const int wflat = (blockIdx.x * blockDim.x + threadIdx.x) >> 5;  // 0..8191
    const int lane  = threadIdx.x & 31;
    const int units_per_col = M_DIM / 2;
    const int total = nh * units_per_col;
    for (int u = wflat; u < total; u += 8192) {
        int c   = g_heavy[u / units_per_col];
        int seg = u % units_per_col;
        int r0  = seg * 2;
        const float* wr = W    + (size_t)c * K_DIM;
        const float* mr = mask + (size_t)c * K_DIM;
        const float* x0 = x + (size_t)r0 * K_DIM;
        float s0 = 0.0f, s1 = 0.0f;
        #pragma unroll 4
        for (int k = lane; k < K_DIM; k += 32) {
            float wv = mr[k] * wr[k];
            s0 += x0[k] * wv;
            s1 += x0[K_DIM + k] * wv;
        }
        #pragma unroll
        for (int d = 16; d; d >>= 1) {
            s0 += __shfl_xor_sync(0xffffffffu, s0, d);
            s1 += __shfl_xor_sync(0xffffffffu, s1, d);
        }
        if (lane == 0) {
            float b = bias[c];
            out[(size_t)r0 * N_DIM + c]       = s0 + b;
            out[(size_t)(r0 + 1) * N_DIM + c] = s1 + b;
        }
    }
}

// ---------------------------------------------------------------------------
extern "C" void kernel_launch(void* const* d_in, const int* in_sizes, int n_in,
                              void* d_out, int out_size) {
    const float* x    = (const float*)d_in[0];  // [16384, 2048]
    const float* W    = (const float*)d_in[1];  // [8192, 2048]
    const float* bias = (const float*)d_in[2];  // [8192]
    const float* mask = (const float*)d_in[3];  // [8192, 2048]
    float* out = (float*)d_out;                 // [16384, 8192]

    float* xT = nullptr;
    cudaGetSymbolAddress((void**)&xT, g_xT);

    rowscan_kernel<<<N_DIM / 8, 256>>>(mask);
    tile_pack_kernel<<<NTILES, 256>>>(W, mask);
    heavy_list_kernel<<<1, 256>>>();
    {
        dim3 tb(32, 8);
        dim3 tg(K_DIM / 32, M_DIM / 32);
        transpose_kernel<<<tg, tb>>>(x, xT);
    }
    {
        dim3 grid(M_DIM / TM, NTILES);
        spmm_kernel<<<grid, 128>>>(xT, bias, out);
    }
    dense_cols_kernel<<<1024, 256>>>(x, W, mask, bias, out);
}